// round 17
// baseline (speedup 1.0000x reference)
#include <cuda_runtime.h>
#include <cstdint>

// Problem constants
#define A_CLS 50
#define C_CL  1024
#define F_LIT 1180
#define B_SMP 512
#define AC    (A_CLS * C_CL)     // 51200 clauses
#define NW    37                 // ceil(1180/32) x-mask words (plain layout)

// Scratch (static __device__ globals — no runtime allocation)
// Plain bit layout: x word w, bit l = x[32w + l].
__device__ unsigned d_xbits[B_SMP][NW];   // full x masks (verify path)
__device__ unsigned d_xwP[4][B_SMP];      // x window bits at offset 8r   (pos screen)
__device__ unsigned d_xwN[4][B_SMP];      // x window bits at offset 8r+4 (neg screen)
__device__ float    d_votes[B_SMP * A_CLS];
__device__ unsigned d_done;               // completion ticket

// ---------------------------------------------------------------------------
// pack_x: one warp per sample row. Loads all 37 words into registers first
// (independent LDGs, one latency exposure), then ballots. Builds the full
// masks plus the 8 shifted 32-bit windows (offsets 8r and 8r+4, r=0..3)
// used by the aligned-window screen. Zeroes votes + ticket.
// ---------------------------------------------------------------------------
__global__ void pack_x_kernel(const float* __restrict__ x) {
    int gtid = blockIdx.x * blockDim.x + threadIdx.x;
    int warp = gtid >> 5;
    int lane = threadIdx.x & 31;
    if (warp < B_SMP) {
        const float* row = x + (size_t)warp * F_LIT;
        float v[NW];
        #pragma unroll
        for (int w = 0; w < NW; w++) {
            int f = w * 32 + lane;
            v[w] = (f < F_LIT) ? __ldg(row + f) : 0.0f;   // independent LDGs
        }
        unsigned w0 = 0, w1 = 0;
        #pragma unroll
        for (int w = 0; w < NW; w++) {
            unsigned bits = __ballot_sync(0xFFFFFFFFu, v[w] > 0.5f);
            if (w == 0) w0 = bits;
            if (w == 1) w1 = bits;
            if (lane == 0) d_xbits[warp][w] = bits;
        }
        if (lane == 0) {
            #pragma unroll
            for (int r = 0; r < 4; r++) {
                // bits [8r, 8r+32) and [8r+4, 8r+36) of (w1:w0)
                d_xwP[r][warp] = __funnelshift_r(w0, w1, 8 * r);
                d_xwN[r][warp] = __funnelshift_r(w0, w1, 8 * r + 4);
            }
        }
    }
    for (int i = gtid; i < B_SMP * A_CLS; i += gridDim.x * blockDim.x)
        d_votes[i] = 0.0f;
    if (gtid == 0) d_done = 0u;
}

// ---------------------------------------------------------------------------
// Screen + verify + (last block) output.
//
// KEY: any 32-literal subset screens conservatively, so each clause is
// screened on the 128B-ALIGNED window of its pos row. Row ac starts at byte
// ac*9440; 9440 mod 128 = 96, so (ac mod 4) determines the aligned window:
// float offset 8*(ac mod 4). ONE aligned line per clause = 51200 lines
// (6.5 MB) vs R16's 205K lines (26 MB) — the quantity the last three rounds
// proved the runtime scales with.
//
// Blocks are residue-grouped (r = blockIdx & 3): all 8 warps screen clauses
// ac ≡ r (mod 4) (8 clauses/warp), sharing one 2KB pos-window x-table and
// one neg-window table in smem. Stage 2 (P=1e-4 per eval, ~0.4/warp): the
// detecting lane scalar-checks the clause's aligned NEG window (another
// 1e-4 filter); survivors (~0.27/launch) get the exact 1180-literal verify.
// Votes via atomicAdd (~never); ticket lets the last block clip + write out.
// ---------------------------------------------------------------------------
__global__ __launch_bounds__(256, 6)
void screen_kernel(const float* __restrict__ ta,
                   const float* __restrict__ clause_sign,
                   const int*   __restrict__ tptr,
                   float*       __restrict__ out) {
    __shared__ __align__(16) unsigned sxp[B_SMP];
    __shared__ __align__(16) unsigned sxn[B_SMP];
    __shared__ bool sLast;

    int r     = blockIdx.x & 3;
    int woffP = 8 * r;            // aligned pos window: floats [8r, 8r+32)
    int woffN = 8 * r + 4;        // aligned neg window: floats [8r+4, 8r+36)

    for (int i = threadIdx.x; i < B_SMP / 4; i += blockDim.x) {
        reinterpret_cast<uint4*>(sxp)[i] = reinterpret_cast<const uint4*>(&d_xwP[r][0])[i];
        reinterpret_cast<uint4*>(sxn)[i] = reinterpret_cast<const uint4*>(&d_xwN[r][0])[i];
    }
    __syncthreads();

    int lane = threadIdx.x & 31;
    int wIdx = (blockIdx.x >> 2) * 8 + (threadIdx.x >> 5);  // 0..1599 per residue
    int m0   = wIdx * 8;                                    // clause ac = r + 4*(m0+k)

    // 8 independent, LINE-ALIGNED 128B loads (one per clause)
    float pv[8];
    #pragma unroll
    for (int k = 0; k < 8; k++) {
        size_t ac = (size_t)(r + 4 * (m0 + k));
        pv[k] = __ldg(ta + ac * (2 * F_LIT) + woffP + lane);
    }
    unsigned p[8];
    #pragma unroll
    for (int k = 0; k < 8; k++)
        p[k] = __ballot_sync(0xFFFFFFFFu, pv[k] > 16.0f);

    // fast screen: viol = included-pos & ~x over the window; candr flags rr
    unsigned candr = 0u;
    #pragma unroll
    for (int rr = 0; rr < 4; rr++) {
        uint4 x = *reinterpret_cast<const uint4*>(&sxp[(rr * 32 + lane) * 4]);
        unsigned m = 0xFFFFFFFFu;
        #pragma unroll
        for (int k = 0; k < 8; k++) {
            unsigned v0 = p[k] & ~x.x;
            unsigned v1 = p[k] & ~x.y;
            unsigned v2 = p[k] & ~x.z;
            unsigned v3 = p[k] & ~x.w;
            m = min(m, min(min(v0, v1), min(v2, v3)));
        }
        if (m == 0u) candr |= 1u << rr;
    }

    // stage 2 + exact verify (P ~ 1e-4 per eval -> ~0.4 candidates per warp)
    if (candr != 0u) {
        #pragma unroll 1
        for (int rr = 0; rr < 4; rr++) {
            if (!((candr >> rr) & 1u)) continue;
            uint4 x = *reinterpret_cast<const uint4*>(&sxp[(rr * 32 + lane) * 4]);
            unsigned xs[4] = {x.x, x.y, x.z, x.w};
            #pragma unroll 1
            for (int k = 0; k < 8; k++) {
                #pragma unroll 1
                for (int j = 0; j < 4; j++) {
                    if ((p[k] & ~xs[j]) != 0u) continue;
                    int b  = (rr * 32 + lane) * 4 + j;
                    int ac = r + 4 * (m0 + k);
                    // stage 2: aligned neg window, scalar build + test
                    const float* negw = ta + (size_t)ac * (2 * F_LIT) + F_LIT + woffN;
                    unsigned nm = 0u;
                    #pragma unroll 1
                    for (int q = 0; q < 32; q++)
                        if (__ldg(negw + q) > 16.0f) nm |= 1u << q;
                    if ((nm & sxn[b]) != 0u) continue;
                    // full exact verify over all 1180 literals
                    const float* pos = ta + (size_t)ac * (2 * F_LIT);
                    const float* neg = pos + F_LIT;
                    bool fire = true;
                    #pragma unroll 1
                    for (int w = 0; w < NW && fire; w++) {
                        unsigned xw = d_xbits[b][w];
                        int base = w * 32;
                        int lim  = (F_LIT - base < 32) ? (F_LIT - base) : 32;
                        #pragma unroll 1
                        for (int l = 0; l < lim; l++) {
                            bool xb = (xw >> l) & 1u;
                            if ((__ldg(pos + base + l) > 16.0f && !xb) ||
                                (__ldg(neg + base + l) > 16.0f &&  xb)) {
                                fire = false; break;
                            }
                        }
                    }
                    if (fire)
                        atomicAdd(&d_votes[b * A_CLS + (ac >> 10)],
                                  __ldg(&clause_sign[ac]));
                }
            }
        }
    }

    // completion ticket; last block clips votes and writes the output
    __syncthreads();
    if (threadIdx.x == 0) {
        __threadfence();                         // release votes
        unsigned t = atomicAdd(&d_done, 1u);
        sLast = (t == gridDim.x - 1);
    }
    __syncthreads();
    if (sLast) {
        __threadfence();                         // acquire votes
        // T dtype is ambiguous (python int in the reference): small
        // non-negative bit-patterns -> int32, anything else -> float32 bits.
        int ti = *tptr;
        float T = (ti >= 0 && ti < (1 << 23)) ? (float)ti : __int_as_float(ti);
        for (int i = threadIdx.x; i < B_SMP * A_CLS; i += blockDim.x) {
            float v = d_votes[i];                // layout [B, A] == out
            out[i] = fminf(fmaxf(v, -T), T);
        }
    }
}

// ---------------------------------------------------------------------------
extern "C" void kernel_launch(void* const* d_in, const int* in_sizes, int n_in,
                              void* d_out, int out_size) {
    const float* x  = (const float*)d_in[0];  // binary_features [512, 1180]
    const float* ta = (const float*)d_in[1];  // ta_state [50, 1024, 2, 1180]
    const float* cs = (const float*)d_in[2];  // clause_sign [50, 1024]
    const int*   Tp = (const int*)  d_in[3];  // T scalar

    (void)in_sizes; (void)n_in; (void)out_size;

    // 1. pack x masks + window tables + zero votes/ticket: 512 warps
    pack_x_kernel<<<64, 256>>>(x);
    // 2. screen: ONE aligned 128B line per clause (6.5 MB), 8 clauses/warp
    screen_kernel<<<800, 256>>>(ta, cs, Tp, (float*)d_out);
}